// round 2
// baseline (speedup 1.0000x reference)
#include <cuda_runtime.h>

#define MULX 64
#define OUT_STRIDE 896
#define PW0f 0.08838834764831845f
#define INV_SQRT3f 0.5773502691896258f

#define A_RT 16
#define A_SMEM_FLOATS (128*320 + A_RT*128 + A_RT*4)
#define A_SMEM_BYTES (A_SMEM_FLOATS * 4)

#define B_RT 32
#define B_SMEM_FLOATS (64*128 + 64*128 + 64*64 + B_RT*64*8 + B_RT*4)
#define B_SMEM_BYTES (B_SMEM_FLOATS * 4)

// ---------------------------------------------------------------------------
// Kernel A: o0 = PW0 * ( [s_a*s0 | dot(v_b,v1)/sqrt3] @ [Wa0; Wb1o0] ) + bias
// Weights (128x320, 160KB) resident in SMEM per block; persistent blocks
// grid-stride over 16-row chunks.
// Thread map: tx in [0,64) -> 5 columns (tx + 64c), ty in [0,4) -> 4 rows.
// ---------------------------------------------------------------------------
__global__ __launch_bounds__(256, 1) void k_o0(
    const float* __restrict__ in1, const float* __restrict__ in2,
    const float* __restrict__ Wa0, const float* __restrict__ Wb1,
    const float* __restrict__ bias, float* __restrict__ out,
    int n, int nChunks)
{
    extern __shared__ float sm[];
    float* sW  = sm;                 // 128*320
    float* sL  = sm + 128*320;       // A_RT*128
    float* sI2 = sL + A_RT*128;      // A_RT*4

    const int tid = threadIdx.x;

    // Stage weights: rows 0..63 = Wa0, rows 64..127 = Wb1o0 (both 64x320)
    {
        const float4* a = (const float4*)Wa0;
        const float4* b = (const float4*)Wb1;
        float4* d = (float4*)sW;
        #pragma unroll
        for (int i = tid; i < 5120; i += 256) { d[i] = a[i]; d[i + 5120] = b[i]; }
    }

    const int tx = tid & 63;
    const int ty = tid >> 6;

    for (int chunk = blockIdx.x; chunk < nChunks; chunk += gridDim.x) {
        const int row0 = chunk * A_RT;
        __syncthreads();   // weights ready (iter 0) / previous compute done

        if (tid < A_RT * 4) {
            int r = tid >> 2, c = tid & 3;
            int nr = row0 + r;
            sI2[tid] = (nr < n) ? in2[nr * 4 + c] : 0.f;
        }
        __syncthreads();

        // Stage activation L: [r][0:64]=s_a*s0, [r][64:128]=dot/sqrt3
        {
            const int u  = tid & 63;
            const int rb = tid >> 6;
            #pragma unroll
            for (int i = 0; i < 4; i++) {
                int r  = rb + 4 * i;
                int nr = row0 + r;
                if (nr < n) {
                    const float* ip = in1 + (size_t)nr * 256;
                    float s0 = sI2[r*4+0], vx = sI2[r*4+1], vy = sI2[r*4+2], vz = sI2[r*4+3];
                    float sa = ip[u];
                    float b0 = ip[64 + 3*u], b1 = ip[65 + 3*u], b2 = ip[66 + 3*u];
                    sL[r*128 + u]      = sa * s0;
                    sL[r*128 + 64 + u] = (b0*vx + b1*vy + b2*vz) * INV_SQRT3f;
                } else {
                    sL[r*128 + u] = 0.f;
                    sL[r*128 + 64 + u] = 0.f;
                }
            }
        }
        __syncthreads();

        float acc[4][5];
        #pragma unroll
        for (int ri = 0; ri < 4; ri++)
            #pragma unroll
            for (int c = 0; c < 5; c++) acc[ri][c] = 0.f;

        #pragma unroll 8
        for (int k = 0; k < 128; k++) {
            float a0 = sL[(ty*4 + 0)*128 + k];
            float a1 = sL[(ty*4 + 1)*128 + k];
            float a2 = sL[(ty*4 + 2)*128 + k];
            float a3 = sL[(ty*4 + 3)*128 + k];
            const float* wr = sW + k*320 + tx;
            #pragma unroll
            for (int c = 0; c < 5; c++) {
                float w = wr[c * 64];
                acc[0][c] += a0 * w;
                acc[1][c] += a1 * w;
                acc[2][c] += a2 * w;
                acc[3][c] += a3 * w;
            }
        }

        #pragma unroll
        for (int ri = 0; ri < 4; ri++) {
            int nr = row0 + ty*4 + ri;
            if (nr >= n) continue;
            float* op = out + (size_t)nr * OUT_STRIDE;
            #pragma unroll
            for (int c = 0; c < 5; c++) {
                int col = tx + c * 64;
                op[col] = PW0f * acc[ri][c] + bias[col];
            }
        }
    }
}

// ---------------------------------------------------------------------------
// Kernel B: o1 (cols 320..703) and o2 (cols 704..895).
//   o1[w,k] = PW0 * ( (s_a@Wa1)[w]*v1[k] + (v_b[:,k]@Wb0)[w]*s0 )
//   o2[w,k] = PW0 * ( cross(v_b,v1)[:,k] @ Wo2 )[w]
// Acts staged per 32-row chunk as [row][u][{sa,vb0,vb1,vb2,cr0,cr1,cr2,pad}]
// Phase1 thread map: wx in [0,32) -> 4 w (wx+32ci), wy in [0,8) -> 4 rows.
// Phase2 thread map: w2g in [0,16) -> 4 w (w2g+16ci), rowg in [0,16) -> 2 rows.
// ---------------------------------------------------------------------------
__global__ __launch_bounds__(256, 1) void k_o12(
    const float* __restrict__ in1, const float* __restrict__ in2,
    const float* __restrict__ Wa1, const float* __restrict__ Wb0,
    const float* __restrict__ Wo2, float* __restrict__ out,
    int n, int nChunks)
{
    extern __shared__ float sm[];
    float* sWa  = sm;            // 64*128
    float* sWb  = sm + 8192;     // 64*128
    float* sWc  = sm + 16384;    // 64*64
    float* sAct = sm + 20480;    // 32*64*8
    float* sI2  = sm + 20480 + 16384;  // 32*4

    const int tid = threadIdx.x;

    // Stage weights
    {
        const float4* a = (const float4*)Wa1;
        const float4* b = (const float4*)Wb0;
        const float4* c = (const float4*)Wo2;
        float4* d = (float4*)sm;
        #pragma unroll
        for (int i = tid; i < 2048; i += 256) { d[i] = a[i]; d[2048 + i] = b[i]; }
        #pragma unroll
        for (int i = tid; i < 1024; i += 256) { d[4096 + i] = c[i]; }
    }

    const int wx = tid & 31, wy = tid >> 5;
    const int w2g = tid & 15, rowg = tid >> 4;

    for (int chunk = blockIdx.x; chunk < nChunks; chunk += gridDim.x) {
        const int row0 = chunk * B_RT;
        __syncthreads();

        if (tid < B_RT * 4) {
            int r = tid >> 2, c = tid & 3;
            int nr = row0 + r;
            sI2[tid] = (nr < n) ? in2[nr * 4 + c] : 0.f;
        }
        __syncthreads();

        // Stage activations
        {
            const int u  = tid & 63;
            const int rb = tid >> 6;
            #pragma unroll
            for (int i = 0; i < 8; i++) {
                int r  = rb + 4 * i;
                int nr = row0 + r;
                float* ap = sAct + (r*64 + u) * 8;
                if (nr < n) {
                    const float* ip = in1 + (size_t)nr * 256;
                    float vx = sI2[r*4+1], vy = sI2[r*4+2], vz = sI2[r*4+3];
                    float sa = ip[u];
                    float b0 = ip[64 + 3*u], b1 = ip[65 + 3*u], b2 = ip[66 + 3*u];
                    ap[0] = sa;
                    ap[1] = b0; ap[2] = b1; ap[3] = b2;
                    ap[4] = b1*vz - b2*vy;
                    ap[5] = b2*vx - b0*vz;
                    ap[6] = b0*vy - b1*vx;
                } else {
                    ap[0]=0.f; ap[1]=0.f; ap[2]=0.f; ap[3]=0.f;
                    ap[4]=0.f; ap[5]=0.f; ap[6]=0.f;
                }
            }
        }
        __syncthreads();

        // ---- Phase 1: o1 ----
        float acc[4][4][4];
        #pragma unroll
        for (int ri = 0; ri < 4; ri++)
            #pragma unroll
            for (int ci = 0; ci < 4; ci++)
                #pragma unroll
                for (int q = 0; q < 4; q++) acc[ri][ci][q] = 0.f;

        #pragma unroll 4
        for (int u = 0; u < 64; u++) {
            float wa[4], wb[4];
            #pragma unroll
            for (int ci = 0; ci < 4; ci++) {
                wa[ci] = sWa[u*128 + wx + 32*ci];
                wb[ci] = sWb[u*128 + wx + 32*ci];
            }
            #pragma unroll
            for (int ri = 0; ri < 4; ri++) {
                float4 av = *(const float4*)(sAct + ((wy*4 + ri)*64 + u) * 8);
                #pragma unroll
                for (int ci = 0; ci < 4; ci++) {
                    acc[ri][ci][0] += av.x * wa[ci];
                    acc[ri][ci][1] += av.y * wb[ci];
                    acc[ri][ci][2] += av.z * wb[ci];
                    acc[ri][ci][3] += av.w * wb[ci];
                }
            }
        }

        #pragma unroll
        for (int ri = 0; ri < 4; ri++) {
            int r = wy*4 + ri;
            int nr = row0 + r;
            if (nr >= n) continue;
            float s0 = sI2[r*4+0], vx = sI2[r*4+1], vy = sI2[r*4+2], vz = sI2[r*4+3];
            float* op = out + (size_t)nr * OUT_STRIDE + 320;
            #pragma unroll
            for (int ci = 0; ci < 4; ci++) {
                int w = wx + 32*ci;
                float A = acc[ri][ci][0];
                op[3*w + 0] = PW0f * (A*vx + acc[ri][ci][1] * s0);
                op[3*w + 1] = PW0f * (A*vy + acc[ri][ci][2] * s0);
                op[3*w + 2] = PW0f * (A*vz + acc[ri][ci][3] * s0);
            }
        }

        // ---- Phase 2: o2 ----
        float a2[2][4][3];
        #pragma unroll
        for (int ri = 0; ri < 2; ri++)
            #pragma unroll
            for (int ci = 0; ci < 4; ci++)
                #pragma unroll
                for (int q = 0; q < 3; q++) a2[ri][ci][q] = 0.f;

        #pragma unroll 4
        for (int u = 0; u < 64; u++) {
            float wc[4];
            #pragma unroll
            for (int ci = 0; ci < 4; ci++) wc[ci] = sWc[u*64 + w2g + 16*ci];
            #pragma unroll
            for (int ri = 0; ri < 2; ri++) {
                float4 cv = *(const float4*)(sAct + ((rowg*2 + ri)*64 + u) * 8 + 4);
                #pragma unroll
                for (int ci = 0; ci < 4; ci++) {
                    a2[ri][ci][0] += cv.x * wc[ci];
                    a2[ri][ci][1] += cv.y * wc[ci];
                    a2[ri][ci][2] += cv.z * wc[ci];
                }
            }
        }

        #pragma unroll
        for (int ri = 0; ri < 2; ri++) {
            int nr = row0 + rowg*2 + ri;
            if (nr >= n) continue;
            float* op = out + (size_t)nr * OUT_STRIDE + 704;
            #pragma unroll
            for (int ci = 0; ci < 4; ci++) {
                int w = w2g + 16*ci;
                op[3*w + 0] = PW0f * a2[ri][ci][0];
                op[3*w + 1] = PW0f * a2[ri][ci][1];
                op[3*w + 2] = PW0f * a2[ri][ci][2];
            }
        }
    }
}

extern "C" void kernel_launch(void* const* d_in, const int* in_sizes, int n_in,
                              void* d_out, int out_size)
{
    const float* in1   = (const float*)d_in[0];
    const float* in2   = (const float*)d_in[1];
    const float* Wa0   = (const float*)d_in[2];
    const float* Wb1o0 = (const float*)d_in[3];
    const float* Wa1   = (const float*)d_in[4];
    const float* Wb0   = (const float*)d_in[5];
    const float* Wo2   = (const float*)d_in[6];
    const float* bias  = (const float*)d_in[7];
    float* out = (float*)d_out;

    const int n = in_sizes[0] / 256;

    cudaFuncSetAttribute(k_o0,  cudaFuncAttributeMaxDynamicSharedMemorySize, A_SMEM_BYTES);
    cudaFuncSetAttribute(k_o12, cudaFuncAttributeMaxDynamicSharedMemorySize, B_SMEM_BYTES);

    int sms = 148;
    cudaDeviceGetAttribute(&sms, cudaDevAttrMultiProcessorCount, 0);

    const int chA = (n + A_RT - 1) / A_RT;
    const int chB = (n + B_RT - 1) / B_RT;
    const int gA = sms < chA ? sms : chA;
    const int gB = sms < chB ? sms : chB;

    k_o0 <<<gA, 256, A_SMEM_BYTES>>>(in1, in2, Wa0, Wb1o0, bias, out, n, chA);
    k_o12<<<gB, 256, B_SMEM_BYTES>>>(in1, in2, Wa1, Wb0, Wo2, out, n, chB);
}